// round 2
// baseline (speedup 1.0000x reference)
#include <cuda_runtime.h>

#define BB 2
#define CC 64
#define CQ 8
#define NN 9216
#define NT 64
#define MT 128

typedef unsigned long long ull;

// Scratch (__device__ globals; allocation-free rule)
__device__ __align__(16) float g_q[BB][NN][CQ];     // [b][n][d]
__device__ __align__(16) float g_k[BB][NN][CQ];     // [b][m][d]
__device__ __align__(16) float g_v[BB][NN][CC];     // [b][n][c], scaled to v/Z by k_vscale
__device__ __align__(16) float g_zp[BB][2][NN];     // partial row sums

// ---------- packed f32x2 helpers ----------
static __device__ __forceinline__ ull pk2(float a, float b) {
    ull r;
    asm("mov.b64 %0, {%1, %2};" : "=l"(r)
        : "r"(__float_as_uint(a)), "r"(__float_as_uint(b)));
    return r;
}
static __device__ __forceinline__ void upk2(ull p, float& a, float& b) {
    unsigned int x, y;
    asm("mov.b64 {%0, %1}, %2;" : "=r"(x), "=r"(y) : "l"(p));
    a = __uint_as_float(x);
    b = __uint_as_float(y);
}
static __device__ __forceinline__ ull ffma2(ull a, ull b, ull c) {
    ull d;
    asm("fma.rn.f32x2 %0, %1, %2, %3;" : "=l"(d) : "l"(a), "l"(b), "l"(c));
    return d;
}
static __device__ __forceinline__ void lds2u64(const void* p, ull& a, ull& b) {
    unsigned s = (unsigned)__cvta_generic_to_shared(p);
    asm("ld.shared.v2.u64 {%0,%1},[%2];" : "=l"(a), "=l"(b) : "r"(s));
}
static __device__ __forceinline__ ull lds1u64(const void* p) {
    ull a;
    unsigned s = (unsigned)__cvta_generic_to_shared(p);
    asm("ld.shared.u64 %0,[%1];" : "=l"(a) : "r"(s));
    return a;
}

// ---------------------------------------------------------------------
// Kernel 1: q/k/v 1x1 convs, split into 3 output sections for occupancy.
// grid 432 = 144 pixel-blocks x 3 sections; 128 threads.
// sec 0: q(8)+k(8); sec 1: v[0:32]; sec 2: v[32:64].
// ---------------------------------------------------------------------
__global__ void __launch_bounds__(128) k_qkv(
    const float* __restrict__ x,
    const float* __restrict__ wq, const float* __restrict__ bq,
    const float* __restrict__ wk, const float* __restrict__ bk,
    const float* __restrict__ wv, const float* __restrict__ bv)
{
    __shared__ float WT[CC][32];   // [c][o]
    __shared__ float bias[32];
    int t = threadIdx.x;
    int pb  = blockIdx.x % 144;
    int sec = blockIdx.x / 144;
    int nout = (sec == 0) ? 16 : 32;

    for (int idx = t; idx < CC * nout; idx += 128) {
        int c = idx / nout, o = idx % nout;
        float w;
        if (sec == 0) w = (o < 8) ? wq[o * CC + c] : wk[(o - 8) * CC + c];
        else if (sec == 1) w = wv[o * CC + c];
        else w = wv[(o + 32) * CC + c];
        WT[c][o] = w;
    }
    if (t < nout) {
        float bb;
        if (sec == 0) bb = (t < 8) ? bq[t] : bk[t - 8];
        else if (sec == 1) bb = bv[t];
        else bb = bv[t + 32];
        bias[t] = bb;
    }
    __syncthreads();

    int pix = pb * 128 + t;
    int b = pix / NN, n = pix % NN;
    const float* xp = x + (size_t)b * CC * NN + n;
    float xr[CC];
#pragma unroll
    for (int c = 0; c < CC; c++) xr[c] = xp[(size_t)c * NN];

    for (int o0 = 0; o0 < nout; o0 += 8) {
        float acc[8];
#pragma unroll
        for (int j = 0; j < 8; j++) acc[j] = bias[o0 + j];
#pragma unroll 16
        for (int c = 0; c < CC; c++) {
            float4 wa = *(const float4*)&WT[c][o0];
            float4 wb = *(const float4*)&WT[c][o0 + 4];
            float xv = xr[c];
            acc[0] = fmaf(wa.x, xv, acc[0]);
            acc[1] = fmaf(wa.y, xv, acc[1]);
            acc[2] = fmaf(wa.z, xv, acc[2]);
            acc[3] = fmaf(wa.w, xv, acc[3]);
            acc[4] = fmaf(wb.x, xv, acc[4]);
            acc[5] = fmaf(wb.y, xv, acc[5]);
            acc[6] = fmaf(wb.z, xv, acc[6]);
            acc[7] = fmaf(wb.w, xv, acc[7]);
        }
        float4 r0 = make_float4(acc[0], acc[1], acc[2], acc[3]);
        float4 r1 = make_float4(acc[4], acc[5], acc[6], acc[7]);
        if (sec == 0) {
            if (o0 == 0) {
                *(float4*)&g_q[b][n][0] = r0;
                *(float4*)&g_q[b][n][4] = r1;
            } else {
                *(float4*)&g_k[b][n][0] = r0;
                *(float4*)&g_k[b][n][4] = r1;
            }
        } else {
            int c0 = (sec == 1 ? 0 : 32) + o0;
            *(float4*)&g_v[b][n][c0]     = r0;
            *(float4*)&g_v[b][n][c0 + 4] = r1;
        }
    }
}

// ---------------------------------------------------------------------
// Kernel 2a: partial Z_n over half the m range. grid 288, 128 threads.
// ---------------------------------------------------------------------
__global__ void __launch_bounds__(128) k_rowsum_p()
{
    __shared__ float ks[CQ][128];   // transposed k tile: ks[d][r] = k[m0+r][d]
    int t = threadIdx.x, bid = blockIdx.x;
    int b = bid / 144;
    int r = bid % 144;
    int half = r / 72, nc = r % 72;
    int n = nc * 128 + t;

    float q[8];
    {
        float4 qa = *(const float4*)&g_q[b][n][0];
        float4 qb = *(const float4*)&g_q[b][n][4];
        q[0] = qa.x; q[1] = qa.y; q[2] = qa.z; q[3] = qa.w;
        q[4] = qb.x; q[5] = qb.y; q[6] = qb.z; q[7] = qb.w;
    }
    ull qq[8];
#pragma unroll
    for (int d = 0; d < 8; d++) qq[d] = pk2(q[d], q[d]);
    ull zero = 0ull;

    float Z = 0.0f;
    int m0 = half * (NN / 2);
    for (int mt = 0; mt < NN / 2; mt += 128) {
        __syncthreads();
        {
            const float4* kr = (const float4*)&g_k[b][m0 + mt + t][0];
            float4 a = kr[0], c = kr[1];
            ks[0][t] = a.x; ks[1][t] = a.y; ks[2][t] = a.z; ks[3][t] = a.w;
            ks[4][t] = c.x; ks[5][t] = c.y; ks[6][t] = c.z; ks[7][t] = c.w;
        }
        __syncthreads();
#pragma unroll 8
        for (int j = 0; j < 64; j++) {
            ull s2 = ffma2(qq[0], lds1u64(&ks[0][2 * j]), zero);
            s2 = ffma2(qq[1], lds1u64(&ks[1][2 * j]), s2);
            s2 = ffma2(qq[2], lds1u64(&ks[2][2 * j]), s2);
            s2 = ffma2(qq[3], lds1u64(&ks[3][2 * j]), s2);
            s2 = ffma2(qq[4], lds1u64(&ks[4][2 * j]), s2);
            s2 = ffma2(qq[5], lds1u64(&ks[5][2 * j]), s2);
            s2 = ffma2(qq[6], lds1u64(&ks[6][2 * j]), s2);
            s2 = ffma2(qq[7], lds1u64(&ks[7][2 * j]), s2);
            float s0, s1;
            upk2(s2, s0, s1);
            Z += __expf(s0) + __expf(s1);
        }
    }
    g_zp[b][half][n] = Z;
}

// ---------------------------------------------------------------------
// Kernel 2b: v[n][:] *= 1/Z_n.  grid 144, 128 threads.
// ---------------------------------------------------------------------
__global__ void __launch_bounds__(128) k_vscale()
{
    int t = threadIdx.x, bid = blockIdx.x;
    int b = bid / 72;
    int n = (bid % 72) * 128 + t;
    float rz = 1.0f / (g_zp[b][0][n] + g_zp[b][1][n]);
    float4* vp = (float4*)&g_v[b][n][0];
#pragma unroll
    for (int i = 0; i < 16; i++) {
        float4 v = vp[i];
        v.x *= rz; v.y *= rz; v.z *= rz; v.w *= rz;
        vp[i] = v;
    }
}

// ---------------------------------------------------------------------
// Kernel 3 (hot): att tile [64ch][128m] per block, fused output proj.
//   phase A: es[n][m] = exp(q_n . k_m)  (FFMA2 over column pairs)
//   phase B: acc[c][m] += (v/Z)[n][c] * es[n][m]  (all operands pre-paired)
//   epilogue: out[o][m] = bo[o] + sum_c wo[o][c] * att[c][m]
// Dynamic SMEM: es[64][128] | wd[64][128] | qd[64][16]  (68 KB)
// ---------------------------------------------------------------------
__global__ void __launch_bounds__(256) k_attn(
    const float* __restrict__ wo, const float* __restrict__ bo,
    float* __restrict__ out)
{
    extern __shared__ float smem[];
    float* es = smem;                 // [n][m] exp tile (later: wod)
    float* wd = smem + NT * MT;       // [n][2c] duplicated v (later: att_s[c][m])
    float* qd = smem + 2 * NT * MT;   // [n][2d] duplicated q

    int t = threadIdx.x, bid = blockIdx.x;
    int b  = bid / (NN / MT);
    int m0 = (bid % (NN / MT)) * MT;

    // phase A identity: column pair {2mp, 2mp+1}, row base rb
    int mp = t & 63;
    int rb = t >> 6;                  // 0..3
    ull kk[8];
    {
        const float4* kA = (const float4*)&g_k[b][m0 + 2 * mp][0];
        const float4* kB = (const float4*)&g_k[b][m0 + 2 * mp + 1][0];
        float4 a0 = kA[0], a1 = kA[1], b0 = kB[0], b1 = kB[1];
        kk[0] = pk2(a0.x, b0.x); kk[1] = pk2(a0.y, b0.y);
        kk[2] = pk2(a0.z, b0.z); kk[3] = pk2(a0.w, b0.w);
        kk[4] = pk2(a1.x, b1.x); kk[5] = pk2(a1.y, b1.y);
        kk[6] = pk2(a1.z, b1.z); kk[7] = pk2(a1.w, b1.w);
    }
    ull zero = 0ull;

    // phase B identity: 4 channels x 8 columns micro-tile
    int mg = t & 15, cg = t >> 4;
    int m8 = mg * 8, c4 = cg * 4;

    ull acc[4][4];
#pragma unroll
    for (int j = 0; j < 4; j++)
#pragma unroll
        for (int p = 0; p < 4; p++) acc[j][p] = 0ull;

    for (int nt = 0; nt < NN; nt += NT) {
        __syncthreads();
        // load v tile duplicated: wd[n][2c],[2c+1] = v[nt+n][c]
#pragma unroll
        for (int i = 0; i < 4; i++) {
            int idx = t + i * 256;            // 0..1023 float4s
            int n = idx >> 4, cidx = (idx & 15) * 4;
            float4 v = *(const float4*)&g_v[b][nt + n][cidx];
            float4* dst = (float4*)&wd[n * MT + 2 * cidx];
            dst[0] = make_float4(v.x, v.x, v.y, v.y);
            dst[1] = make_float4(v.z, v.z, v.w, v.w);
        }
        // load q tile duplicated: qd[n][2d],[2d+1] = q[nt+n][d]
        if (t < 128) {
            int n = t >> 1, d0 = (t & 1) * 4;
            float4 q = *(const float4*)&g_q[b][nt + n][d0];
            float4* dst = (float4*)&qd[n * 16 + 2 * d0];
            dst[0] = make_float4(q.x, q.x, q.y, q.y);
            dst[1] = make_float4(q.z, q.z, q.w, q.w);
        }
        __syncthreads();

        // ---- phase A: 16 rows x 2 cols per thread, packed ----
#pragma unroll 4
        for (int i = 0; i < 16; i++) {
            int n = rb + i * 4;
            ull q0, q1, q2, q3, q4, q5, q6, q7;
            lds2u64(&qd[n * 16 + 0],  q0, q1);
            lds2u64(&qd[n * 16 + 4],  q2, q3);
            lds2u64(&qd[n * 16 + 8],  q4, q5);
            lds2u64(&qd[n * 16 + 12], q6, q7);
            ull s2 = ffma2(q0, kk[0], zero);
            s2 = ffma2(q1, kk[1], s2);
            s2 = ffma2(q2, kk[2], s2);
            s2 = ffma2(q3, kk[3], s2);
            s2 = ffma2(q4, kk[4], s2);
            s2 = ffma2(q5, kk[5], s2);
            s2 = ffma2(q6, kk[6], s2);
            s2 = ffma2(q7, kk[7], s2);
            float s0, s1;
            upk2(s2, s0, s1);
            *(float2*)&es[n * MT + 2 * mp] = make_float2(__expf(s0), __expf(s1));
        }
        __syncthreads();

        // ---- phase B: zero packing MOVs ----
#pragma unroll 4
        for (int n = 0; n < NT; n++) {
            ull e01, e23, e45, e67;
            lds2u64(&es[n * MT + m8],     e01, e23);
            lds2u64(&es[n * MT + m8 + 4], e45, e67);
#pragma unroll
            for (int j = 0; j < 4; j++) {
                ull w = lds1u64(&wd[n * MT + 2 * (c4 + j)]);
                acc[j][0] = ffma2(e01, w, acc[j][0]);
                acc[j][1] = ffma2(e23, w, acc[j][1]);
                acc[j][2] = ffma2(e45, w, acc[j][2]);
                acc[j][3] = ffma2(e67, w, acc[j][3]);
            }
        }
    }

    // ---- epilogue: fused output projection ----
    __syncthreads();
    // att_s[c][m] <- acc (reuse wd)
#pragma unroll
    for (int j = 0; j < 4; j++)
#pragma unroll
        for (int p = 0; p < 4; p++)
            *(ull*)&wd[(c4 + j) * MT + m8 + 2 * p] = acc[j][p];
    // wod[c][2o],[2o+1] = wo[o][c]  (reuse es)
#pragma unroll
    for (int i = 0; i < 4; i++) {
        int idx = t + i * 256;           // 1024 float4s of wo
        int o = idx >> 4, cidx = (idx & 15) * 4;
        float4 w = *(const float4*)&wo[o * CC + cidx];
        *(float2*)&es[(cidx + 0) * MT + 2 * o] = make_float2(w.x, w.x);
        *(float2*)&es[(cidx + 1) * MT + 2 * o] = make_float2(w.y, w.y);
        *(float2*)&es[(cidx + 2) * MT + 2 * o] = make_float2(w.z, w.z);
        *(float2*)&es[(cidx + 3) * MT + 2 * o] = make_float2(w.w, w.w);
    }
    float bias[4];
#pragma unroll
    for (int j = 0; j < 4; j++) bias[j] = bo[c4 + j];
    __syncthreads();

    ull oacc[4][4];
#pragma unroll
    for (int j = 0; j < 4; j++)
#pragma unroll
        for (int p = 0; p < 4; p++) oacc[j][p] = 0ull;

#pragma unroll 4
    for (int c = 0; c < CC; c++) {
        ull a01, a23, a45, a67;
        lds2u64(&wd[c * MT + m8],     a01, a23);
        lds2u64(&wd[c * MT + m8 + 4], a45, a67);
#pragma unroll
        for (int j = 0; j < 4; j++) {
            ull w = lds1u64(&es[c * MT + 2 * (c4 + j)]);
            oacc[j][0] = ffma2(a01, w, oacc[j][0]);
            oacc[j][1] = ffma2(a23, w, oacc[j][1]);
            oacc[j][2] = ffma2(a45, w, oacc[j][2]);
            oacc[j][3] = ffma2(a67, w, oacc[j][3]);
        }
    }

#pragma unroll
    for (int j = 0; j < 4; j++) {
        float r[8];
        upk2(oacc[j][0], r[0], r[1]);
        upk2(oacc[j][1], r[2], r[3]);
        upk2(oacc[j][2], r[4], r[5]);
        upk2(oacc[j][3], r[6], r[7]);
#pragma unroll
        for (int p = 0; p < 8; p++) r[p] += bias[j];
        float* op = out + ((size_t)b * CC + c4 + j) * NN + m0 + m8;
        *(float4*)&op[0] = make_float4(r[0], r[1], r[2], r[3]);
        *(float4*)&op[4] = make_float4(r[4], r[5], r[6], r[7]);
    }
}

// ---------------------------------------------------------------------
extern "C" void kernel_launch(void* const* d_in, const int* in_sizes, int n_in,
                              void* d_out, int out_size)
{
    const float* x  = (const float*)d_in[0];
    const float* wq = (const float*)d_in[1];
    const float* bq = (const float*)d_in[2];
    const float* wk = (const float*)d_in[3];
    const float* bk = (const float*)d_in[4];
    const float* wv = (const float*)d_in[5];
    const float* bv = (const float*)d_in[6];
    const float* wo = (const float*)d_in[7];
    const float* bo = (const float*)d_in[8];
    float* out = (float*)d_out;

    static int smem_set = 0;
    if (!smem_set) {
        cudaFuncSetAttribute(k_attn, cudaFuncAttributeMaxDynamicSharedMemorySize,
                             (2 * NT * MT + NT * 16) * sizeof(float));
        smem_set = 1;
    }

    k_qkv     <<<432, 128>>>(x, wq, bq, wk, bk, wv, bv);
    k_rowsum_p<<<288, 128>>>();
    k_vscale  <<<144, 128>>>();
    k_attn    <<<144, 256, (2 * NT * MT + NT * 16) * sizeof(float)>>>(wo, bo, out);
}

// round 3
// speedup vs baseline: 1.2361x; 1.2361x over previous
#include <cuda_runtime.h>

#define BB 2
#define CC 64
#define CQ 8
#define NN 9216
#define NT 64
#define MT 128

typedef unsigned long long ull;

// Scratch (__device__ globals; allocation-free rule)
__device__ __align__(16) float g_q[BB][NN][CQ];     // [b][n][d]
__device__ __align__(16) float g_k[BB][NN][CQ];     // [b][m][d]
__device__ __align__(16) float g_v[BB][NN][CC];     // [b][n][c] (unscaled)
__device__ __align__(16) float g_u[BB][NN][CC];     // U[n][o] = (wo @ v_n)/Z_n
__device__ __align__(16) float g_zp[BB][2][NN];     // partial row sums

// ---------- packed f32x2 helpers ----------
static __device__ __forceinline__ ull pk2(float a, float b) {
    ull r;
    asm("mov.b64 %0, {%1, %2};" : "=l"(r)
        : "r"(__float_as_uint(a)), "r"(__float_as_uint(b)));
    return r;
}
static __device__ __forceinline__ void upk2(ull p, float& a, float& b) {
    unsigned int x, y;
    asm("mov.b64 {%0, %1}, %2;" : "=r"(x), "=r"(y) : "l"(p));
    a = __uint_as_float(x);
    b = __uint_as_float(y);
}
static __device__ __forceinline__ ull ffma2(ull a, ull b, ull c) {
    ull d;
    asm("fma.rn.f32x2 %0, %1, %2, %3;" : "=l"(d) : "l"(a), "l"(b), "l"(c));
    return d;
}
static __device__ __forceinline__ void lds2u64(const void* p, ull& a, ull& b) {
    unsigned s = (unsigned)__cvta_generic_to_shared(p);
    asm("ld.shared.v2.u64 {%0,%1},[%2];" : "=l"(a), "=l"(b) : "r"(s));
}
static __device__ __forceinline__ ull lds1u64(const void* p) {
    ull a;
    unsigned s = (unsigned)__cvta_generic_to_shared(p);
    asm("ld.shared.u64 %0,[%1];" : "=l"(a) : "r"(s));
    return a;
}

// ---------------------------------------------------------------------
// Kernel 1: q/k/v 1x1 convs, 3 output sections. grid 432, 128 threads.
// ---------------------------------------------------------------------
__global__ void __launch_bounds__(128) k_qkv(
    const float* __restrict__ x,
    const float* __restrict__ wq, const float* __restrict__ bq,
    const float* __restrict__ wk, const float* __restrict__ bk,
    const float* __restrict__ wv, const float* __restrict__ bv)
{
    __shared__ float WT[CC][32];
    __shared__ float bias[32];
    int t = threadIdx.x;
    int pb  = blockIdx.x % 144;
    int sec = blockIdx.x / 144;
    int nout = (sec == 0) ? 16 : 32;

    for (int idx = t; idx < CC * nout; idx += 128) {
        int c = idx / nout, o = idx % nout;
        float w;
        if (sec == 0) w = (o < 8) ? wq[o * CC + c] : wk[(o - 8) * CC + c];
        else if (sec == 1) w = wv[o * CC + c];
        else w = wv[(o + 32) * CC + c];
        WT[c][o] = w;
    }
    if (t < nout) {
        float bb;
        if (sec == 0) bb = (t < 8) ? bq[t] : bk[t - 8];
        else if (sec == 1) bb = bv[t];
        else bb = bv[t + 32];
        bias[t] = bb;
    }
    __syncthreads();

    int pix = pb * 128 + t;
    int b = pix / NN, n = pix % NN;
    const float* xp = x + (size_t)b * CC * NN + n;
    float xr[CC];
#pragma unroll
    for (int c = 0; c < CC; c++) xr[c] = xp[(size_t)c * NN];

    for (int o0 = 0; o0 < nout; o0 += 8) {
        float acc[8];
#pragma unroll
        for (int j = 0; j < 8; j++) acc[j] = bias[o0 + j];
#pragma unroll 16
        for (int c = 0; c < CC; c++) {
            float4 wa = *(const float4*)&WT[c][o0];
            float4 wb = *(const float4*)&WT[c][o0 + 4];
            float xv = xr[c];
            acc[0] = fmaf(wa.x, xv, acc[0]);
            acc[1] = fmaf(wa.y, xv, acc[1]);
            acc[2] = fmaf(wa.z, xv, acc[2]);
            acc[3] = fmaf(wa.w, xv, acc[3]);
            acc[4] = fmaf(wb.x, xv, acc[4]);
            acc[5] = fmaf(wb.y, xv, acc[5]);
            acc[6] = fmaf(wb.z, xv, acc[6]);
            acc[7] = fmaf(wb.w, xv, acc[7]);
        }
        float4 r0 = make_float4(acc[0], acc[1], acc[2], acc[3]);
        float4 r1 = make_float4(acc[4], acc[5], acc[6], acc[7]);
        if (sec == 0) {
            if (o0 == 0) {
                *(float4*)&g_q[b][n][0] = r0;
                *(float4*)&g_q[b][n][4] = r1;
            } else {
                *(float4*)&g_k[b][n][0] = r0;
                *(float4*)&g_k[b][n][4] = r1;
            }
        } else {
            int c0 = (sec == 1 ? 0 : 32) + o0;
            *(float4*)&g_v[b][n][c0]     = r0;
            *(float4*)&g_v[b][n][c0 + 4] = r1;
        }
    }
}

// ---------------------------------------------------------------------
// Kernel 2: partial Z_n over half the m range. grid 288, 128 threads.
// ---------------------------------------------------------------------
__global__ void __launch_bounds__(128) k_rowsum_p()
{
    __shared__ float ks[CQ][128];
    int t = threadIdx.x, bid = blockIdx.x;
    int b = bid / 144;
    int r = bid % 144;
    int half = r / 72, nc = r % 72;
    int n = nc * 128 + t;

    float q[8];
    {
        float4 qa = *(const float4*)&g_q[b][n][0];
        float4 qb = *(const float4*)&g_q[b][n][4];
        q[0] = qa.x; q[1] = qa.y; q[2] = qa.z; q[3] = qa.w;
        q[4] = qb.x; q[5] = qb.y; q[6] = qb.z; q[7] = qb.w;
    }
    ull qq[8];
#pragma unroll
    for (int d = 0; d < 8; d++) qq[d] = pk2(q[d], q[d]);
    ull zero = 0ull;

    float Z = 0.0f;
    int m0 = half * (NN / 2);
    for (int mt = 0; mt < NN / 2; mt += 128) {
        __syncthreads();
        {
            const float4* kr = (const float4*)&g_k[b][m0 + mt + t][0];
            float4 a = kr[0], c = kr[1];
            ks[0][t] = a.x; ks[1][t] = a.y; ks[2][t] = a.z; ks[3][t] = a.w;
            ks[4][t] = c.x; ks[5][t] = c.y; ks[6][t] = c.z; ks[7][t] = c.w;
        }
        __syncthreads();
#pragma unroll 8
        for (int j = 0; j < 64; j++) {
            ull s2 = ffma2(qq[0], lds1u64(&ks[0][2 * j]), zero);
            s2 = ffma2(qq[1], lds1u64(&ks[1][2 * j]), s2);
            s2 = ffma2(qq[2], lds1u64(&ks[2][2 * j]), s2);
            s2 = ffma2(qq[3], lds1u64(&ks[3][2 * j]), s2);
            s2 = ffma2(qq[4], lds1u64(&ks[4][2 * j]), s2);
            s2 = ffma2(qq[5], lds1u64(&ks[5][2 * j]), s2);
            s2 = ffma2(qq[6], lds1u64(&ks[6][2 * j]), s2);
            s2 = ffma2(qq[7], lds1u64(&ks[7][2 * j]), s2);
            float s0, s1;
            upk2(s2, s0, s1);
            Z += __expf(s0) + __expf(s1);
        }
    }
    g_zp[b][half][n] = Z;
}

// ---------------------------------------------------------------------
// Kernel 2b: U[n][o] = (wo @ v_n) / Z_n.  grid 144, 128 threads.
// ---------------------------------------------------------------------
__global__ void __launch_bounds__(128) k_uproj(const float* __restrict__ wo)
{
    __shared__ float WT[CC][CC];   // [c][o] = wo[o][c]
    int t = threadIdx.x, bid = blockIdx.x;
    for (int idx = t; idx < CC * CC; idx += 128) {
        int c = idx / CC, o = idx % CC;
        WT[c][o] = wo[o * CC + c];
    }
    __syncthreads();

    int b = bid / 72;
    int n = (bid % 72) * 128 + t;
    float rz = 1.0f / (g_zp[b][0][n] + g_zp[b][1][n]);

    float xr[CC];
    {
        const float4* vp = (const float4*)&g_v[b][n][0];
#pragma unroll
        for (int i = 0; i < 16; i++) *(float4*)&xr[i * 4] = vp[i];
    }

    for (int o0 = 0; o0 < CC; o0 += 8) {
        float acc[8];
#pragma unroll
        for (int j = 0; j < 8; j++) acc[j] = 0.0f;
#pragma unroll 16
        for (int c = 0; c < CC; c++) {
            float4 wa = *(const float4*)&WT[c][o0];
            float4 wb = *(const float4*)&WT[c][o0 + 4];
            float xv = xr[c];
            acc[0] = fmaf(wa.x, xv, acc[0]);
            acc[1] = fmaf(wa.y, xv, acc[1]);
            acc[2] = fmaf(wa.z, xv, acc[2]);
            acc[3] = fmaf(wa.w, xv, acc[3]);
            acc[4] = fmaf(wb.x, xv, acc[4]);
            acc[5] = fmaf(wb.y, xv, acc[5]);
            acc[6] = fmaf(wb.z, xv, acc[6]);
            acc[7] = fmaf(wb.w, xv, acc[7]);
        }
        *(float4*)&g_u[b][n][o0]     = make_float4(acc[0]*rz, acc[1]*rz, acc[2]*rz, acc[3]*rz);
        *(float4*)&g_u[b][n][o0 + 4] = make_float4(acc[4]*rz, acc[5]*rz, acc[6]*rz, acc[7]*rz);
    }
}

// ---------------------------------------------------------------------
// Kernel 3 (hot): out tile [64o][128m] per block.
//   phase A: es[n][m] = exp(q_n . k_m)
//   phase B: out[o][m] = bo[o] + sum_n U[n][o] * es[n][m]
// Warp tile 64m x 16o; thread tile (4m + 4m) x 4o; all LDS conflict-free.
// Dynamic SMEM: es[64][128] | ud[64][128] | qd[64][16]  (68 KB)
// ---------------------------------------------------------------------
__global__ void __launch_bounds__(256) k_attn(
    const float* __restrict__ bo, float* __restrict__ out)
{
    extern __shared__ float smem[];
    float* es = smem;                 // [n][m] exp tile
    float* ud = smem + NT * MT;       // [n][2o] duplicated U
    float* qd = smem + 2 * NT * MT;   // [n][2d] duplicated q

    int t = threadIdx.x, bid = blockIdx.x;
    int b  = bid / (NN / MT);
    int m0 = (bid % (NN / MT)) * MT;

    // phase A identity: column pair {2mp, 2mp+1}, row base rb
    int mp = t & 63;
    int rb = t >> 6;                  // 0..3
    ull kk[8];
    {
        const float4* kA = (const float4*)&g_k[b][m0 + 2 * mp][0];
        const float4* kB = (const float4*)&g_k[b][m0 + 2 * mp + 1][0];
        float4 a0 = kA[0], a1 = kA[1], b0 = kB[0], b1 = kB[1];
        kk[0] = pk2(a0.x, b0.x); kk[1] = pk2(a0.y, b0.y);
        kk[2] = pk2(a0.z, b0.z); kk[3] = pk2(a0.w, b0.w);
        kk[4] = pk2(a1.x, b1.x); kk[5] = pk2(a1.y, b1.y);
        kk[6] = pk2(a1.z, b1.z); kk[7] = pk2(a1.w, b1.w);
    }
    ull zero = 0ull;

    // phase B identity: warp tile 64m x 16o, lanes 8(mg) x 4(og)
    int lane = t & 31, wa = t >> 5;
    int mg = lane & 7, og = lane >> 3;
    int mA = (wa & 1) * 64 + mg * 4;      // first 4-col chunk
    int mB = mA + 32;                     // second 4-col chunk
    int o4 = (wa >> 1) * 16 + og * 4;

    ull acc[4][4];
#pragma unroll
    for (int j = 0; j < 4; j++) {
        float bj = bo[o4 + j];
        ull bp = pk2(bj, bj);
        acc[j][0] = bp;
#pragma unroll
        for (int p = 1; p < 4; p++) acc[j][p] = 0ull;
    }

    for (int nt = 0; nt < NN; nt += NT) {
        __syncthreads();
        // ud[n][2o],[2o+1] = U[nt+n][o]
#pragma unroll
        for (int i = 0; i < 4; i++) {
            int idx = t + i * 256;
            int n = idx >> 4, cidx = (idx & 15) * 4;
            float4 v = *(const float4*)&g_u[b][nt + n][cidx];
            float4* dst = (float4*)&ud[n * MT + 2 * cidx];
            dst[0] = make_float4(v.x, v.x, v.y, v.y);
            dst[1] = make_float4(v.z, v.z, v.w, v.w);
        }
        // qd[n][2d],[2d+1] = q[nt+n][d]
        if (t < 128) {
            int n = t >> 1, d0 = (t & 1) * 4;
            float4 q = *(const float4*)&g_q[b][nt + n][d0];
            float4* dst = (float4*)&qd[n * 16 + 2 * d0];
            dst[0] = make_float4(q.x, q.x, q.y, q.y);
            dst[1] = make_float4(q.z, q.z, q.w, q.w);
        }
        __syncthreads();

        // ---- phase A: 16 rows x 2 cols per thread, packed ----
#pragma unroll 4
        for (int i = 0; i < 16; i++) {
            int n = rb + i * 4;
            ull q0, q1, q2, q3, q4, q5, q6, q7;
            lds2u64(&qd[n * 16 + 0],  q0, q1);
            lds2u64(&qd[n * 16 + 4],  q2, q3);
            lds2u64(&qd[n * 16 + 8],  q4, q5);
            lds2u64(&qd[n * 16 + 12], q6, q7);
            ull s2 = ffma2(q0, kk[0], zero);
            s2 = ffma2(q1, kk[1], s2);
            s2 = ffma2(q2, kk[2], s2);
            s2 = ffma2(q3, kk[3], s2);
            s2 = ffma2(q4, kk[4], s2);
            s2 = ffma2(q5, kk[5], s2);
            s2 = ffma2(q6, kk[6], s2);
            s2 = ffma2(q7, kk[7], s2);
            float s0, s1;
            upk2(s2, s0, s1);
            *(float2*)&es[n * MT + 2 * mp] = make_float2(__expf(s0), __expf(s1));
        }
        __syncthreads();

        // ---- phase B: conflict-free, broadcast-dedup'd ----
#pragma unroll 4
        for (int n = 0; n < NT; n++) {
            ull e0, e1, e2, e3, w0, w1, w2, w3;
            lds2u64(&es[n * MT + mA], e0, e1);
            lds2u64(&es[n * MT + mB], e2, e3);
            lds2u64(&ud[n * MT + 2 * o4],     w0, w1);
            lds2u64(&ud[n * MT + 2 * o4 + 4], w2, w3);
            acc[0][0] = ffma2(e0, w0, acc[0][0]);
            acc[0][1] = ffma2(e1, w0, acc[0][1]);
            acc[0][2] = ffma2(e2, w0, acc[0][2]);
            acc[0][3] = ffma2(e3, w0, acc[0][3]);
            acc[1][0] = ffma2(e0, w1, acc[1][0]);
            acc[1][1] = ffma2(e1, w1, acc[1][1]);
            acc[1][2] = ffma2(e2, w1, acc[1][2]);
            acc[1][3] = ffma2(e3, w1, acc[1][3]);
            acc[2][0] = ffma2(e0, w2, acc[2][0]);
            acc[2][1] = ffma2(e1, w2, acc[2][1]);
            acc[2][2] = ffma2(e2, w2, acc[2][2]);
            acc[2][3] = ffma2(e3, w2, acc[2][3]);
            acc[3][0] = ffma2(e0, w3, acc[3][0]);
            acc[3][1] = ffma2(e1, w3, acc[3][1]);
            acc[3][2] = ffma2(e2, w3, acc[3][2]);
            acc[3][3] = ffma2(e3, w3, acc[3][3]);
        }
    }

    // ---- store: out[b][o][m0 + mA/mB] ----
#pragma unroll
    for (int j = 0; j < 4; j++) {
        float r[8];
        upk2(acc[j][0], r[0], r[1]);
        upk2(acc[j][1], r[2], r[3]);
        upk2(acc[j][2], r[4], r[5]);
        upk2(acc[j][3], r[6], r[7]);
        float* op = out + ((size_t)b * CC + o4 + j) * NN + m0;
        *(float4*)&op[mA] = make_float4(r[0], r[1], r[2], r[3]);
        *(float4*)&op[mB] = make_float4(r[4], r[5], r[6], r[7]);
    }
}

// ---------------------------------------------------------------------
extern "C" void kernel_launch(void* const* d_in, const int* in_sizes, int n_in,
                              void* d_out, int out_size)
{
    const float* x  = (const float*)d_in[0];
    const float* wq = (const float*)d_in[1];
    const float* bq = (const float*)d_in[2];
    const float* wk = (const float*)d_in[3];
    const float* bk = (const float*)d_in[4];
    const float* wv = (const float*)d_in[5];
    const float* bv = (const float*)d_in[6];
    const float* wo = (const float*)d_in[7];
    const float* bo = (const float*)d_in[8];
    float* out = (float*)d_out;

    static int smem_set = 0;
    if (!smem_set) {
        cudaFuncSetAttribute(k_attn, cudaFuncAttributeMaxDynamicSharedMemorySize,
                             (2 * NT * MT + NT * 16) * sizeof(float));
        smem_set = 1;
    }

    k_qkv     <<<432, 128>>>(x, wq, bq, wk, bk, wv, bv);
    k_rowsum_p<<<288, 128>>>();
    k_uproj   <<<144, 128>>>(wo);
    k_attn    <<<144, 256, (2 * NT * MT + NT * 16) * sizeof(float)>>>(bo, out);
}

// round 5
// speedup vs baseline: 1.2366x; 1.0003x over previous
#include <cuda_runtime.h>

#define BB 2
#define CC 64
#define CQ 8
#define NN 9216
#define NT 64
#define MT 128

typedef unsigned long long ull;

// Scratch (__device__ globals; allocation-free rule)
__device__ __align__(16) float g_q[BB][NN][CQ];     // [b][n][d]
__device__ __align__(16) float g_k[BB][NN][CQ];     // [b][m][d]
__device__ __align__(16) float g_v[BB][NN][CC];     // [b][n][c] (unscaled)
__device__ __align__(16) float g_u[BB][NN][CC];     // U[n][o] = (wo @ v_n)/Z_n
__device__ __align__(16) float g_zp[BB][2][NN];     // partial row sums

// ---------- packed f32x2 helpers ----------
static __device__ __forceinline__ ull pk2(float a, float b) {
    ull r;
    asm("mov.b64 %0, {%1, %2};" : "=l"(r)
        : "r"(__float_as_uint(a)), "r"(__float_as_uint(b)));
    return r;
}
static __device__ __forceinline__ void upk2(ull p, float& a, float& b) {
    unsigned int x, y;
    asm("mov.b64 {%0, %1}, %2;" : "=r"(x), "=r"(y) : "l"(p));
    a = __uint_as_float(x);
    b = __uint_as_float(y);
}
static __device__ __forceinline__ ull ffma2(ull a, ull b, ull c) {
    ull d;
    asm("fma.rn.f32x2 %0, %1, %2, %3;" : "=l"(d) : "l"(a), "l"(b), "l"(c));
    return d;
}
static __device__ __forceinline__ void lds2u64(const void* p, ull& a, ull& b) {
    unsigned s = (unsigned)__cvta_generic_to_shared(p);
    asm("ld.shared.v2.u64 {%0,%1},[%2];" : "=l"(a), "=l"(b) : "r"(s));
}
static __device__ __forceinline__ ull lds1u64(const void* p) {
    ull a;
    unsigned s = (unsigned)__cvta_generic_to_shared(p);
    asm("ld.shared.u64 %0,[%1];" : "=l"(a) : "r"(s));
    return a;
}

// ---------------------------------------------------------------------
// Kernel 1: q/k/v 1x1 convs, 3 output sections. grid 432, 128 threads.
// ---------------------------------------------------------------------
__global__ void __launch_bounds__(128) k_qkv(
    const float* __restrict__ x,
    const float* __restrict__ wq, const float* __restrict__ bq,
    const float* __restrict__ wk, const float* __restrict__ bk,
    const float* __restrict__ wv, const float* __restrict__ bv)
{
    __shared__ float WT[CC][32];
    __shared__ float bias[32];
    int t = threadIdx.x;
    int pb  = blockIdx.x % 144;
    int sec = blockIdx.x / 144;
    int nout = (sec == 0) ? 16 : 32;

    for (int idx = t; idx < CC * nout; idx += 128) {
        int c = idx / nout, o = idx % nout;
        float w;
        if (sec == 0) w = (o < 8) ? wq[o * CC + c] : wk[(o - 8) * CC + c];
        else if (sec == 1) w = wv[o * CC + c];
        else w = wv[(o + 32) * CC + c];
        WT[c][o] = w;
    }
    if (t < nout) {
        float bb;
        if (sec == 0) bb = (t < 8) ? bq[t] : bk[t - 8];
        else if (sec == 1) bb = bv[t];
        else bb = bv[t + 32];
        bias[t] = bb;
    }
    __syncthreads();

    int pix = pb * 128 + t;
    int b = pix / NN, n = pix % NN;
    const float* xp = x + (size_t)b * CC * NN + n;
    float xr[CC];
#pragma unroll
    for (int c = 0; c < CC; c++) xr[c] = xp[(size_t)c * NN];

    for (int o0 = 0; o0 < nout; o0 += 8) {
        float acc[8];
#pragma unroll
        for (int j = 0; j < 8; j++) acc[j] = bias[o0 + j];
#pragma unroll 16
        for (int c = 0; c < CC; c++) {
            float4 wa = *(const float4*)&WT[c][o0];
            float4 wb = *(const float4*)&WT[c][o0 + 4];
            float xv = xr[c];
            acc[0] = fmaf(wa.x, xv, acc[0]);
            acc[1] = fmaf(wa.y, xv, acc[1]);
            acc[2] = fmaf(wa.z, xv, acc[2]);
            acc[3] = fmaf(wa.w, xv, acc[3]);
            acc[4] = fmaf(wb.x, xv, acc[4]);
            acc[5] = fmaf(wb.y, xv, acc[5]);
            acc[6] = fmaf(wb.z, xv, acc[6]);
            acc[7] = fmaf(wb.w, xv, acc[7]);
        }
        float4 r0 = make_float4(acc[0], acc[1], acc[2], acc[3]);
        float4 r1 = make_float4(acc[4], acc[5], acc[6], acc[7]);
        if (sec == 0) {
            if (o0 == 0) {
                *(float4*)&g_q[b][n][0] = r0;
                *(float4*)&g_q[b][n][4] = r1;
            } else {
                *(float4*)&g_k[b][n][0] = r0;
                *(float4*)&g_k[b][n][4] = r1;
            }
        } else {
            int c0 = (sec == 1 ? 0 : 32) + o0;
            *(float4*)&g_v[b][n][c0]     = r0;
            *(float4*)&g_v[b][n][c0 + 4] = r1;
        }
    }
}

// ---------------------------------------------------------------------
// Kernel 2: partial Z_n over half the m range. grid 288, 128 threads.
// ---------------------------------------------------------------------
__global__ void __launch_bounds__(128) k_rowsum_p()
{
    __shared__ float ks[CQ][128];
    int t = threadIdx.x, bid = blockIdx.x;
    int b = bid / 144;
    int r = bid % 144;
    int half = r / 72, nc = r % 72;
    int n = nc * 128 + t;

    float q[8];
    {
        float4 qa = *(const float4*)&g_q[b][n][0];
        float4 qb = *(const float4*)&g_q[b][n][4];
        q[0] = qa.x; q[1] = qa.y; q[2] = qa.z; q[3] = qa.w;
        q[4] = qb.x; q[5] = qb.y; q[6] = qb.z; q[7] = qb.w;
    }
    ull qq[8];
#pragma unroll
    for (int d = 0; d < 8; d++) qq[d] = pk2(q[d], q[d]);
    ull zero = 0ull;

    float Z = 0.0f;
    int m0 = half * (NN / 2);
    for (int mt = 0; mt < NN / 2; mt += 128) {
        __syncthreads();
        {
            const float4* kr = (const float4*)&g_k[b][m0 + mt + t][0];
            float4 a = kr[0], c = kr[1];
            ks[0][t] = a.x; ks[1][t] = a.y; ks[2][t] = a.z; ks[3][t] = a.w;
            ks[4][t] = c.x; ks[5][t] = c.y; ks[6][t] = c.z; ks[7][t] = c.w;
        }
        __syncthreads();
#pragma unroll 8
        for (int j = 0; j < 64; j++) {
            ull s2 = ffma2(qq[0], lds1u64(&ks[0][2 * j]), zero);
            s2 = ffma2(qq[1], lds1u64(&ks[1][2 * j]), s2);
            s2 = ffma2(qq[2], lds1u64(&ks[2][2 * j]), s2);
            s2 = ffma2(qq[3], lds1u64(&ks[3][2 * j]), s2);
            s2 = ffma2(qq[4], lds1u64(&ks[4][2 * j]), s2);
            s2 = ffma2(qq[5], lds1u64(&ks[5][2 * j]), s2);
            s2 = ffma2(qq[6], lds1u64(&ks[6][2 * j]), s2);
            s2 = ffma2(qq[7], lds1u64(&ks[7][2 * j]), s2);
            float s0, s1;
            upk2(s2, s0, s1);
            Z += __expf(s0) + __expf(s1);
        }
    }
    g_zp[b][half][n] = Z;
}

// ---------------------------------------------------------------------
// Kernel 2b: U[n][o] = (wo @ v_n) / Z_n.  grid 144, 128 threads.
// ---------------------------------------------------------------------
__global__ void __launch_bounds__(128) k_uproj(const float* __restrict__ wo)
{
    __shared__ float WT[CC][CC];   // [c][o] = wo[o][c]
    int t = threadIdx.x, bid = blockIdx.x;
    for (int idx = t; idx < CC * CC; idx += 128) {
        int c = idx / CC, o = idx % CC;
        WT[c][o] = wo[o * CC + c];
    }
    __syncthreads();

    int b = bid / 72;
    int n = (bid % 72) * 128 + t;
    float rz = 1.0f / (g_zp[b][0][n] + g_zp[b][1][n]);

    float xr[CC];
    {
        const float4* vp = (const float4*)&g_v[b][n][0];
#pragma unroll
        for (int i = 0; i < 16; i++) *(float4*)&xr[i * 4] = vp[i];
    }

    for (int o0 = 0; o0 < CC; o0 += 8) {
        float acc[8];
#pragma unroll
        for (int j = 0; j < 8; j++) acc[j] = 0.0f;
#pragma unroll 16
        for (int c = 0; c < CC; c++) {
            float4 wa = *(const float4*)&WT[c][o0];
            float4 wb = *(const float4*)&WT[c][o0 + 4];
            float xv = xr[c];
            acc[0] = fmaf(wa.x, xv, acc[0]);
            acc[1] = fmaf(wa.y, xv, acc[1]);
            acc[2] = fmaf(wa.z, xv, acc[2]);
            acc[3] = fmaf(wa.w, xv, acc[3]);
            acc[4] = fmaf(wb.x, xv, acc[4]);
            acc[5] = fmaf(wb.y, xv, acc[5]);
            acc[6] = fmaf(wb.z, xv, acc[6]);
            acc[7] = fmaf(wb.w, xv, acc[7]);
        }
        *(float4*)&g_u[b][n][o0]     = make_float4(acc[0]*rz, acc[1]*rz, acc[2]*rz, acc[3]*rz);
        *(float4*)&g_u[b][n][o0 + 4] = make_float4(acc[4]*rz, acc[5]*rz, acc[6]*rz, acc[7]*rz);
    }
}

// ---------------------------------------------------------------------
// Kernel 3 (hot): out tile [64o][128m] per block.
//   phase A: es[n][m] = exp(q_n . k_m)
//   phase B: out[o][m] = bo[o] + sum_n U[n][o] * es[n][m]
// Warp tile 64m x 16o; thread tile (4m + 4m) x 4o; all LDS conflict-free.
// Dynamic SMEM: es[64][128] | ud[64][128] | qd[64][16]  (68 KB)
// ---------------------------------------------------------------------
__global__ void __launch_bounds__(256) k_attn(
    const float* __restrict__ bo, float* __restrict__ out)
{
    extern __shared__ float smem[];
    float* es = smem;                 // [n][m] exp tile
    float* ud = smem + NT * MT;       // [n][2o] duplicated U
    float* qd = smem + 2 * NT * MT;   // [n][2d] duplicated q

    int t = threadIdx.x, bid = blockIdx.x;
    int b  = bid / (NN / MT);
    int m0 = (bid % (NN / MT)) * MT;

    // phase A identity: column pair {2mp, 2mp+1}, row base rb
    int mp = t & 63;
    int rb = t >> 6;                  // 0..3
    ull kk[8];
    {
        const float4* kA = (const float4*)&g_k[b][m0 + 2 * mp][0];
        const float4* kB = (const float4*)&g_k[b][m0 + 2 * mp + 1][0];
        float4 a0 = kA[0], a1 = kA[1], b0 = kB[0], b1 = kB[1];
        kk[0] = pk2(a0.x, b0.x); kk[1] = pk2(a0.y, b0.y);
        kk[2] = pk2(a0.z, b0.z); kk[3] = pk2(a0.w, b0.w);
        kk[4] = pk2(a1.x, b1.x); kk[5] = pk2(a1.y, b1.y);
        kk[6] = pk2(a1.z, b1.z); kk[7] = pk2(a1.w, b1.w);
    }
    ull zero = 0ull;

    // phase B identity: warp tile 64m x 16o, lanes 8(mg) x 4(og)
    int lane = t & 31, wa = t >> 5;
    int mg = lane & 7, og = lane >> 3;
    int mA = (wa & 1) * 64 + mg * 4;      // first 4-col chunk
    int mB = mA + 32;                     // second 4-col chunk
    int o4 = (wa >> 1) * 16 + og * 4;

    ull acc[4][4];
#pragma unroll
    for (int j = 0; j < 4; j++) {
        float bj = bo[o4 + j];
        ull bp = pk2(bj, bj);
        acc[j][0] = bp;
#pragma unroll
        for (int p = 1; p < 4; p++) acc[j][p] = 0ull;
    }

    for (int nt = 0; nt < NN; nt += NT) {
        __syncthreads();
        // ud[n][2o],[2o+1] = U[nt+n][o]
#pragma unroll
        for (int i = 0; i < 4; i++) {
            int idx = t + i * 256;
            int n = idx >> 4, cidx = (idx & 15) * 4;
            float4 v = *(const float4*)&g_u[b][nt + n][cidx];
            float4* dst = (float4*)&ud[n * MT + 2 * cidx];
            dst[0] = make_float4(v.x, v.x, v.y, v.y);
            dst[1] = make_float4(v.z, v.z, v.w, v.w);
        }
        // qd[n][2d],[2d+1] = q[nt+n][d]
        if (t < 128) {
            int n = t >> 1, d0 = (t & 1) * 4;
            float4 q = *(const float4*)&g_q[b][nt + n][d0];
            float4* dst = (float4*)&qd[n * 16 + 2 * d0];
            dst[0] = make_float4(q.x, q.x, q.y, q.y);
            dst[1] = make_float4(q.z, q.z, q.w, q.w);
        }
        __syncthreads();

        // ---- phase A: 16 rows x 2 cols per thread, packed ----
#pragma unroll 4
        for (int i = 0; i < 16; i++) {
            int n = rb + i * 4;
            ull q0, q1, q2, q3, q4, q5, q6, q7;
            lds2u64(&qd[n * 16 + 0],  q0, q1);
            lds2u64(&qd[n * 16 + 4],  q2, q3);
            lds2u64(&qd[n * 16 + 8],  q4, q5);
            lds2u64(&qd[n * 16 + 12], q6, q7);
            ull s2 = ffma2(q0, kk[0], zero);
            s2 = ffma2(q1, kk[1], s2);
            s2 = ffma2(q2, kk[2], s2);
            s2 = ffma2(q3, kk[3], s2);
            s2 = ffma2(q4, kk[4], s2);
            s2 = ffma2(q5, kk[5], s2);
            s2 = ffma2(q6, kk[6], s2);
            s2 = ffma2(q7, kk[7], s2);
            float s0, s1;
            upk2(s2, s0, s1);
            *(float2*)&es[n * MT + 2 * mp] = make_float2(__expf(s0), __expf(s1));
        }
        __syncthreads();

        // ---- phase B: conflict-free, broadcast-dedup'd ----
#pragma unroll 4
        for (int n = 0; n < NT; n++) {
            ull e0, e1, e2, e3, w0, w1, w2, w3;
            lds2u64(&es[n * MT + mA], e0, e1);
            lds2u64(&es[n * MT + mB], e2, e3);
            lds2u64(&ud[n * MT + 2 * o4],     w0, w1);
            lds2u64(&ud[n * MT + 2 * o4 + 4], w2, w3);
            acc[0][0] = ffma2(e0, w0, acc[0][0]);
            acc[0][1] = ffma2(e1, w0, acc[0][1]);
            acc[0][2] = ffma2(e2, w0, acc[0][2]);
            acc[0][3] = ffma2(e3, w0, acc[0][3]);
            acc[1][0] = ffma2(e0, w1, acc[1][0]);
            acc[1][1] = ffma2(e1, w1, acc[1][1]);
            acc[1][2] = ffma2(e2, w1, acc[1][2]);
            acc[1][3] = ffma2(e3, w1, acc[1][3]);
            acc[2][0] = ffma2(e0, w2, acc[2][0]);
            acc[2][1] = ffma2(e1, w2, acc[2][1]);
            acc[2][2] = ffma2(e2, w2, acc[2][2]);
            acc[2][3] = ffma2(e3, w2, acc[2][3]);
            acc[3][0] = ffma2(e0, w3, acc[3][0]);
            acc[3][1] = ffma2(e1, w3, acc[3][1]);
            acc[3][2] = ffma2(e2, w3, acc[3][2]);
            acc[3][3] = ffma2(e3, w3, acc[3][3]);
        }
    }

    // ---- store: out[b][o][m0 + mA/mB] ----
#pragma unroll
    for (int j = 0; j < 4; j++) {
        float r[8];
        upk2(acc[j][0], r[0], r[1]);
        upk2(acc[j][1], r[2], r[3]);
        upk2(acc[j][2], r[4], r[5]);
        upk2(acc[j][3], r[6], r[7]);
        float* op = out + ((size_t)b * CC + o4 + j) * NN + m0;
        *(float4*)&op[mA] = make_float4(r[0], r[1], r[2], r[3]);
        *(float4*)&op[mB] = make_float4(r[4], r[5], r[6], r[7]);
    }
}

// ---------------------------------------------------------------------
extern "C" void kernel_launch(void* const* d_in, const int* in_sizes, int n_in,
                              void* d_out, int out_size)
{
    const float* x  = (const float*)d_in[0];
    const float* wq = (const float*)d_in[1];
    const float* bq = (const float*)d_in[2];
    const float* wk = (const float*)d_in[3];
    const float* bk = (const float*)d_in[4];
    const float* wv = (const float*)d_in[5];
    const float* bv = (const float*)d_in[6];
    const float* wo = (const float*)d_in[7];
    const float* bo = (const float*)d_in[8];
    float* out = (float*)d_out;

    static int smem_set = 0;
    if (!smem_set) {
        cudaFuncSetAttribute(k_attn, cudaFuncAttributeMaxDynamicSharedMemorySize,
                             (2 * NT * MT + NT * 16) * sizeof(float));
        smem_set = 1;
    }

    k_qkv     <<<432, 128>>>(x, wq, bq, wk, bk, wv, bv);
    k_rowsum_p<<<288, 128>>>();
    k_uproj   <<<144, 128>>>(wo);
    k_attn    <<<144, 256, (2 * NT * MT + NT * 16) * sizeof(float)>>>(bo, out);
}